// round 7
// baseline (speedup 1.0000x reference)
#include <cuda_runtime.h>
#include <cuda_bf16.h>
#include <math_constants.h>

// Problem constants
#define TLEN   1024
#define SLEN   1024
#define BSZ    16
#define EMB    256
#define NH     8
#define HD     32
#define BH     (BSZ*NH)        // 128
#define MROWS  (TLEN*BSZ)      // 16384
#define QSCALE 0.17677669529663688f   // 1/sqrt(32)

typedef unsigned long long u64;

// ---- packed fp32x2 helpers --------------------------------------------------
__device__ __forceinline__ u64 pk2(float x, float y) {
    u64 r; asm("mov.b64 %0, {%1,%2};" : "=l"(r) : "f"(x), "f"(y)); return r;
}
__device__ __forceinline__ void fma2(u64& d, u64 a, u64 b) {
    asm("fma.rn.f32x2 %0, %1, %2, %0;" : "+l"(d) : "l"(a), "l"(b));
}
__device__ __forceinline__ float2 up2(u64 v) {
    float2 r; asm("mov.b64 {%0,%1}, %2;" : "=f"(r.x), "=f"(r.y) : "l"(v)); return r;
}

// ---------------- scratch (device globals; no allocation allowed) ----------
__device__ float g_QKV[(size_t)MROWS * 768];   // [t*16+b][sec*256 + h*32 + d], q pre-scaled
__device__ float g_ctx[(size_t)MROWS * EMB];   // [t*16+b][h*32+d]

// ---------------- zero kernel ----------------------------------------------
__global__ void zero_f4(float4* __restrict__ p, int n4) {
    int i = blockIdx.x * blockDim.x + threadIdx.x;
    int stride = gridDim.x * blockDim.x;
    float4 z = make_float4(0.f, 0.f, 0.f, 0.f);
    for (; i < n4; i += stride) p[i] = z;
}

// ---------------- fp32 tiled GEMM (f32x2, reg-prefetch):  out = X.W^T + b ---
#define XS_STR 132
#define WS_STR 68

template<int MODE>
__global__ __launch_bounds__(256)
void gemm_k(const float* __restrict__ Xq, const float* __restrict__ Xk,
            const float* __restrict__ Xv, const float* __restrict__ W,
            const float* __restrict__ bias, float* __restrict__ outp)
{
    __shared__ float Xs[16 * XS_STR];
    __shared__ float Ws[16 * WS_STR];

    const int n0 = blockIdx.x * 64;
    const int m0 = blockIdx.y * 128;
    const int tid = threadIdx.x;
    const int tx = tid & 15;
    const int ty = tid >> 4;

    const float* X;
    if (MODE == 0) {
        int sec = n0 >> 8;
        X = (sec == 0) ? Xq : (sec == 1 ? Xk : Xv);
    } else {
        X = g_ctx;
    }

    const int xr0 = tid >> 2;
    const int xkq = (tid & 3) * 4;
    const int wn  = tid >> 2;
    float4 xv0, xv1, wv;
    {
        xv0 = *reinterpret_cast<const float4*>(X + (size_t)(m0 + xr0) * 256 + xkq);
        xv1 = *reinterpret_cast<const float4*>(X + (size_t)(m0 + xr0 + 64) * 256 + xkq);
        wv  = *reinterpret_cast<const float4*>(W + (size_t)(n0 + wn) * 256 + xkq);
    }

    u64 acc2[16];
#pragma unroll
    for (int i = 0; i < 16; i++) acc2[i] = 0ull;

    for (int kc = 0; kc < 16; kc++) {
        Xs[(xkq + 0) * XS_STR + xr0] = xv0.x;
        Xs[(xkq + 1) * XS_STR + xr0] = xv0.y;
        Xs[(xkq + 2) * XS_STR + xr0] = xv0.z;
        Xs[(xkq + 3) * XS_STR + xr0] = xv0.w;
        Xs[(xkq + 0) * XS_STR + xr0 + 64] = xv1.x;
        Xs[(xkq + 1) * XS_STR + xr0 + 64] = xv1.y;
        Xs[(xkq + 2) * XS_STR + xr0 + 64] = xv1.z;
        Xs[(xkq + 3) * XS_STR + xr0 + 64] = xv1.w;
        Ws[(xkq + 0) * WS_STR + wn] = wv.x;
        Ws[(xkq + 1) * WS_STR + wn] = wv.y;
        Ws[(xkq + 2) * WS_STR + wn] = wv.z;
        Ws[(xkq + 3) * WS_STR + wn] = wv.w;
        __syncthreads();

        if (kc < 15) {
            const int k0n = (kc + 1) * 16 + xkq;
            xv0 = *reinterpret_cast<const float4*>(X + (size_t)(m0 + xr0) * 256 + k0n);
            xv1 = *reinterpret_cast<const float4*>(X + (size_t)(m0 + xr0 + 64) * 256 + k0n);
            wv  = *reinterpret_cast<const float4*>(W + (size_t)(n0 + wn) * 256 + k0n);
        }

#pragma unroll
        for (int kk = 0; kk < 16; kk++) {
            const u64* ap = reinterpret_cast<const u64*>(&Xs[kk * XS_STR + ty * 8]);
            u64 am0 = ap[0], am1 = ap[1], am2 = ap[2], am3 = ap[3];
            float4 b0 = *reinterpret_cast<const float4*>(&Ws[kk * WS_STR + tx * 4]);
            u64 bb0 = pk2(b0.x, b0.x), bb1 = pk2(b0.y, b0.y);
            u64 bb2 = pk2(b0.z, b0.z), bb3 = pk2(b0.w, b0.w);
            fma2(acc2[ 0], am0, bb0); fma2(acc2[ 1], am0, bb1);
            fma2(acc2[ 2], am0, bb2); fma2(acc2[ 3], am0, bb3);
            fma2(acc2[ 4], am1, bb0); fma2(acc2[ 5], am1, bb1);
            fma2(acc2[ 6], am1, bb2); fma2(acc2[ 7], am1, bb3);
            fma2(acc2[ 8], am2, bb0); fma2(acc2[ 9], am2, bb1);
            fma2(acc2[10], am2, bb2); fma2(acc2[11], am2, bb3);
            fma2(acc2[12], am3, bb0); fma2(acc2[13], am3, bb1);
            fma2(acc2[14], am3, bb2); fma2(acc2[15], am3, bb3);
        }
        __syncthreads();
    }

#pragma unroll
    for (int p = 0; p < 4; p++) {
#pragma unroll
        for (int jn = 0; jn < 4; jn++) {
            float2 v2 = up2(acc2[p * 4 + jn]);
            int ng = n0 + tx * 4 + jn;
            float bv = bias[ng];
#pragma unroll
            for (int half = 0; half < 2; half++) {
                int r = m0 + ty * 8 + 2 * p + half;
                float v = (half ? v2.y : v2.x) + bv;
                if (MODE == 0) {
                    if (ng < 256) v *= QSCALE;
                    g_QKV[(size_t)r * 768 + ng] = v;
                } else {
                    outp[(size_t)r * 256 + ng] = v;
                }
            }
        }
    }
}

// ---------------- fused attention: scores + sparsemax + AV + avg weights ----
// 128 blocks (one per bh), 384 threads (12 warps, 3/SMSP).
// Warp owns full rows; R=4 rows share each K LDS.128 (8 FFMA2 per LDS).
// sK XOR-swizzled: K[s][d] at d*1024 + (((s>>2)^(d>>2))<<2) + (s&3).
__global__ __launch_bounds__(384, 1)
void attn_kernel(float* __restrict__ attnw /* [16,1024,1024] */)
{
    extern __shared__ float sK[];   // 32*1024 floats
    const int bh   = blockIdx.x;
    const int tid  = threadIdx.x;
    const int lane = tid & 31;
    const int wid  = tid >> 5;      // 0..11
    const int b    = bh >> 3;
    const int h    = bh & 7;

    const float* QKV = g_QKV;
    const int qoff = h * 32;
    const int koff = 256 + h * 32;
    const int voff = 512 + h * 32;

    // ---- load K[bh] into swizzled-transposed smem (conflict-free) ----
    for (int e4 = tid; e4 < (SLEN * HD) / 4; e4 += 384) {
        int s  = e4 >> 3;
        int dq = (e4 & 7) * 4;
        float4 v = *reinterpret_cast<const float4*>(
            QKV + ((size_t)s * 16 + b) * 768 + koff + dq);
        int g = s >> 2;
        int sj = s & 3;
        sK[(dq + 0) * 1024 + ((g ^ ((dq + 0) >> 2)) << 2) + sj] = v.x;
        sK[(dq + 1) * 1024 + ((g ^ ((dq + 1) >> 2)) << 2) + sj] = v.y;
        sK[(dq + 2) * 1024 + ((g ^ ((dq + 2) >> 2)) << 2) + sj] = v.z;
        sK[(dq + 3) * 1024 + ((g ^ ((dq + 3) >> 2)) << 2) + sj] = v.w;
    }
    __syncthreads();

    // 256 groups of 4 rows, striped over 12 warps
    for (int g4 = wid; g4 < 256; g4 += 12) {
        const int t0 = g4 * 4;

        float qv[4];
#pragma unroll
        for (int r = 0; r < 4; r++)
            qv[r] = QKV[((size_t)(t0 + r) * 16 + b) * 768 + qoff + lane];

        // acc[r][2c+half]: packed score pair, s = c*128 + lane*4 + (2*half..+1)
        u64 acc[4][16];
#pragma unroll
        for (int r = 0; r < 4; r++)
#pragma unroll
            for (int j = 0; j < 16; j++) acc[r][j] = 0ull;

#pragma unroll 2
        for (int d = 0; d < 32; d++) {
            u64 qq[4];
#pragma unroll
            for (int r = 0; r < 4; r++) {
                float qd = __shfl_sync(0xffffffffu, qv[r], d);
                qq[r] = pk2(qd, qd);
            }
            const float* basep = sK + d * 1024 + ((lane ^ (d >> 2)) << 2);
#pragma unroll
            for (int c = 0; c < 8; c++) {
                ulonglong2 k4 = *reinterpret_cast<const ulonglong2*>(basep + c * 128);
#pragma unroll
                for (int r = 0; r < 4; r++) {
                    fma2(acc[r][2 * c + 0], qq[r], k4.x);
                    fma2(acc[r][2 * c + 1], qq[r], k4.y);
                }
            }
        }

        // ---- per-row sparsemax + AV + averaged attention weights ----
#pragma unroll 1
        for (int r = 0; r < 4; r++) {
            float a[32];
#pragma unroll
            for (int c = 0; c < 8; c++) {
                float2 p0 = up2(acc[r][2 * c + 0]);
                float2 p1 = up2(acc[r][2 * c + 1]);
                a[4 * c + 0] = p0.x; a[4 * c + 1] = p0.y;
                a[4 * c + 2] = p1.x; a[4 * c + 3] = p1.y;
            }

            // Michelot from tau = max(z) - 1 (valid support superset)
            float mx = a[0];
#pragma unroll
            for (int i = 1; i < 32; i++) mx = fmaxf(mx, a[i]);
#pragma unroll
            for (int o = 16; o > 0; o >>= 1)
                mx = fmaxf(mx, __shfl_xor_sync(0xffffffffu, mx, o));
            float tau = mx - 1.0f;
            int prevc = -1;

            for (int iter = 0; iter < 64; iter++) {
                float s = 0.f;
                int   c = 0;
#pragma unroll
                for (int i = 0; i < 32; i++) {
                    if (a[i] > tau) { s += a[i]; c++; }
                }
#pragma unroll
                for (int o = 16; o > 0; o >>= 1) {
                    s += __shfl_xor_sync(0xffffffffu, s, o);
                    c += __shfl_xor_sync(0xffffffffu, c, o);
                }
                if (c == prevc) break;
                tau = (s - 1.0f) / (float)c;
                prevc = c;
            }

            const int t = t0 + r;
            float* awrow = attnw + ((size_t)b * TLEN + t) * SLEN;
            const float* Vbase = QKV + (size_t)voff + (size_t)b * 768;
            float outv = 0.f;
#pragma unroll
            for (int i = 0; i < 32; i++) {
                float w = (a[i] > tau) ? (a[i] - tau) : 0.f;
                unsigned m = __ballot_sync(0xffffffffu, w > 0.f);
                if (w > 0.f) {
                    int s_me = (i >> 2) * 128 + lane * 4 + (i & 3);
                    atomicAdd(awrow + s_me, 0.125f * w);
                }
                while (m) {
                    int j = __ffs(m) - 1;
                    m &= m - 1;
                    float wj = __shfl_sync(0xffffffffu, w, j);
                    int s = (i >> 2) * 128 + j * 4 + (i & 3);
                    outv = fmaf(wj, Vbase[(size_t)s * 12288 + lane], outv);
                }
            }
            g_ctx[((size_t)t * BSZ + b) * EMB + h * HD + lane] = outv;
        }
    }
}

// ---------------- launcher ---------------------------------------------------
extern "C" void kernel_launch(void* const* d_in, const int* in_sizes, int n_in,
                              void* d_out, int out_size)
{
    const float* query = (const float*)d_in[0];
    const float* key   = (const float*)d_in[1];
    const float* value = (const float*)d_in[2];
    const float* Win   = (const float*)d_in[3];
    const float* bin   = (const float*)d_in[4];
    const float* Wout  = (const float*)d_in[5];
    const float* bout  = (const float*)d_in[6];

    float* outp  = (float*)d_out;                         // [1024,16,256]
    float* attnw = outp + (size_t)MROWS * EMB;            // [16,1024,1024]

    const int ATTN_SMEM = 32 * 1024 * (int)sizeof(float);
    cudaFuncSetAttribute(attn_kernel, cudaFuncAttributeMaxDynamicSharedMemorySize,
                         ATTN_SMEM);

    // 1) zero averaged attention-weights output (sparse atomics accumulate into it)
    zero_f4<<<2048, 256>>>((float4*)attnw, (int)((size_t)BSZ * TLEN * SLEN / 4));

    // 2) QKV projection (M=16384, N=768, K=256)
    gemm_k<0><<<dim3(768 / 64, MROWS / 128), 256>>>(query, key, value, Win, bin, nullptr);

    // 3) fused attention: scores + sparsemax + AV + avg attn weights
    attn_kernel<<<BH, 384, ATTN_SMEM>>>(attnw);

    // 4) output projection (M=16384, N=256, K=256)
    gemm_k<1><<<dim3(256 / 64, MROWS / 128), 256>>>(nullptr, nullptr, nullptr, Wout, bout, outp);
}

// round 8
// speedup vs baseline: 1.1313x; 1.1313x over previous
#include <cuda_runtime.h>
#include <cuda_bf16.h>
#include <math_constants.h>

// Problem constants
#define TLEN   1024
#define SLEN   1024
#define BSZ    16
#define EMB    256
#define NH     8
#define HD     32
#define BH     (BSZ*NH)        // 128
#define MROWS  (TLEN*BSZ)      // 16384
#define QSCALE 0.17677669529663688f   // 1/sqrt(32)

typedef unsigned long long u64;

// ---- packed fp32x2 helpers --------------------------------------------------
__device__ __forceinline__ u64 pk2(float x, float y) {
    u64 r; asm("mov.b64 %0, {%1,%2};" : "=l"(r) : "f"(x), "f"(y)); return r;
}
__device__ __forceinline__ void fma2(u64& d, u64 a, u64 b) {
    asm("fma.rn.f32x2 %0, %1, %2, %0;" : "+l"(d) : "l"(a), "l"(b));
}
__device__ __forceinline__ float2 up2(u64 v) {
    float2 r; asm("mov.b64 {%0,%1}, %2;" : "=f"(r.x), "=f"(r.y) : "l"(v)); return r;
}

// ---------------- scratch (device globals; no allocation allowed) ----------
__device__ float g_QKV[(size_t)MROWS * 768];   // [t*16+b][sec*256 + h*32 + d], q pre-scaled
__device__ float g_ctx[(size_t)MROWS * EMB];   // [t*16+b][h*32+d]

// ---------------- zero kernel ----------------------------------------------
__global__ void zero_f4(float4* __restrict__ p, int n4) {
    int i = blockIdx.x * blockDim.x + threadIdx.x;
    int stride = gridDim.x * blockDim.x;
    float4 z = make_float4(0.f, 0.f, 0.f, 0.f);
    for (; i < n4; i += stride) p[i] = z;
}

// ---------------- fp32 tiled GEMM (f32x2, 128x128 tile):  out = X.W^T + b ---
// M=16384, K=256.  BM=128, BN=128, BK=16, 256 threads, 8x8 micro tile.
// MODE 0: out -> g_QKV (q section scaled), X chosen per 256-wide n-section
// MODE 1: X = g_ctx, out -> outp [r*256+n]
#define GS_STR 132

template<int MODE>
__global__ __launch_bounds__(256)
void gemm_k(const float* __restrict__ Xq, const float* __restrict__ Xk,
            const float* __restrict__ Xv, const float* __restrict__ W,
            const float* __restrict__ bias, float* __restrict__ outp)
{
    __shared__ float Xs[16 * GS_STR];
    __shared__ float Ws[16 * GS_STR];

    const int n0 = blockIdx.x * 128;
    const int m0 = blockIdx.y * 128;
    const int tid = threadIdx.x;
    const int tx = tid & 15;        // n micro: tx*8
    const int ty = tid >> 4;        // m micro: ty*8

    const float* X;
    if (MODE == 0) {
        int sec = n0 >> 8;          // 128-tiles never straddle a 256 section
        X = (sec == 0) ? Xq : (sec == 1 ? Xk : Xv);
    } else {
        X = g_ctx;
    }

    // load coordinates: X rows r, r+64; W rows r, r+64; k offset kq..kq+3
    const int lr  = tid >> 2;            // 0..63
    const int kq  = (tid & 3) * 4;

    float4 xv0, xv1, wv0, wv1;
    xv0 = *reinterpret_cast<const float4*>(X + (size_t)(m0 + lr) * 256 + kq);
    xv1 = *reinterpret_cast<const float4*>(X + (size_t)(m0 + lr + 64) * 256 + kq);
    wv0 = *reinterpret_cast<const float4*>(W + (size_t)(n0 + lr) * 256 + kq);
    wv1 = *reinterpret_cast<const float4*>(W + (size_t)(n0 + lr + 64) * 256 + kq);

    // acc[p][jn]: u64 = rows (2p,2p+1) of micro-tile, col jn (8 n)
    u64 acc[32];
#pragma unroll
    for (int i = 0; i < 32; i++) acc[i] = 0ull;

    for (int kc = 0; kc < 16; kc++) {
#pragma unroll
        for (int j = 0; j < 4; j++) {
            float xj0 = (j == 0) ? xv0.x : (j == 1) ? xv0.y : (j == 2) ? xv0.z : xv0.w;
            float xj1 = (j == 0) ? xv1.x : (j == 1) ? xv1.y : (j == 2) ? xv1.z : xv1.w;
            float wj0 = (j == 0) ? wv0.x : (j == 1) ? wv0.y : (j == 2) ? wv0.z : wv0.w;
            float wj1 = (j == 0) ? wv1.x : (j == 1) ? wv1.y : (j == 2) ? wv1.z : wv1.w;
            Xs[(kq + j) * GS_STR + lr]      = xj0;
            Xs[(kq + j) * GS_STR + lr + 64] = xj1;
            Ws[(kq + j) * GS_STR + lr]      = wj0;
            Ws[(kq + j) * GS_STR + lr + 64] = wj1;
        }
        __syncthreads();

        if (kc < 15) {
            const int k0n = (kc + 1) * 16 + kq;
            xv0 = *reinterpret_cast<const float4*>(X + (size_t)(m0 + lr) * 256 + k0n);
            xv1 = *reinterpret_cast<const float4*>(X + (size_t)(m0 + lr + 64) * 256 + k0n);
            wv0 = *reinterpret_cast<const float4*>(W + (size_t)(n0 + lr) * 256 + k0n);
            wv1 = *reinterpret_cast<const float4*>(W + (size_t)(n0 + lr + 64) * 256 + k0n);
        }

#pragma unroll
        for (int kk = 0; kk < 16; kk++) {
            const u64* ap = reinterpret_cast<const u64*>(&Xs[kk * GS_STR + ty * 8]);
            u64 am0 = ap[0], am1 = ap[1], am2 = ap[2], am3 = ap[3];
            float4 b0 = *reinterpret_cast<const float4*>(&Ws[kk * GS_STR + tx * 8]);
            float4 b1 = *reinterpret_cast<const float4*>(&Ws[kk * GS_STR + tx * 8 + 4]);
            u64 bb0 = pk2(b0.x, b0.x), bb1 = pk2(b0.y, b0.y);
            u64 bb2 = pk2(b0.z, b0.z), bb3 = pk2(b0.w, b0.w);
            u64 bb4 = pk2(b1.x, b1.x), bb5 = pk2(b1.y, b1.y);
            u64 bb6 = pk2(b1.z, b1.z), bb7 = pk2(b1.w, b1.w);
#pragma unroll
            for (int p = 0; p < 4; p++) {
                u64 am = (p == 0) ? am0 : (p == 1) ? am1 : (p == 2) ? am2 : am3;
                fma2(acc[p * 8 + 0], am, bb0); fma2(acc[p * 8 + 1], am, bb1);
                fma2(acc[p * 8 + 2], am, bb2); fma2(acc[p * 8 + 3], am, bb3);
                fma2(acc[p * 8 + 4], am, bb4); fma2(acc[p * 8 + 5], am, bb5);
                fma2(acc[p * 8 + 6], am, bb6); fma2(acc[p * 8 + 7], am, bb7);
            }
        }
        __syncthreads();
    }

    // ---- epilogue: vectorized row stores (8 consecutive n per thread) ----
    const int ngb = n0 + tx * 8;
    float4 bv0 = *reinterpret_cast<const float4*>(bias + ngb);
    float4 bv1 = *reinterpret_cast<const float4*>(bias + ngb + 4);
    const float scl = (MODE == 0 && n0 < 256) ? QSCALE : 1.0f;

#pragma unroll
    for (int p = 0; p < 4; p++) {
#pragma unroll
        for (int half = 0; half < 2; half++) {
            int r = m0 + ty * 8 + 2 * p + half;
            float v[8];
#pragma unroll
            for (int jn = 0; jn < 8; jn++) {
                float2 v2 = up2(acc[p * 8 + jn]);
                v[jn] = (half ? v2.y : v2.x);
            }
            v[0] += bv0.x; v[1] += bv0.y; v[2] += bv0.z; v[3] += bv0.w;
            v[4] += bv1.x; v[5] += bv1.y; v[6] += bv1.z; v[7] += bv1.w;
#pragma unroll
            for (int jn = 0; jn < 8; jn++) v[jn] *= scl;
            float* dst = (MODE == 0) ? (g_QKV + (size_t)r * 768 + ngb)
                                     : (outp + (size_t)r * 256 + ngb);
            *reinterpret_cast<float4*>(dst)     = make_float4(v[0], v[1], v[2], v[3]);
            *reinterpret_cast<float4*>(dst + 4) = make_float4(v[4], v[5], v[6], v[7]);
        }
    }
}

// ---------------- fused attention (round-6 verbatim: best known, 830us) -----
// 128 blocks (one per bh), 512 threads (16 warps), warp owns full rows (R=2).
// sK layout XOR-swizzled: element K[s][d] at  d*1024 + (((s>>2)^(d>>2))<<2) + (s&3)
__global__ __launch_bounds__(512, 1)
void attn_kernel(float* __restrict__ attnw /* [16,1024,1024] */)
{
    extern __shared__ float sK[];   // 32*1024 floats
    const int bh   = blockIdx.x;
    const int tid  = threadIdx.x;
    const int lane = tid & 31;
    const int wid  = tid >> 5;      // 0..15
    const int b    = bh >> 3;
    const int h    = bh & 7;

    const float* QKV = g_QKV;
    const int qoff = h * 32;
    const int koff = 256 + h * 32;
    const int voff = 512 + h * 32;

    // ---- load K[bh] into swizzled-transposed smem (conflict-free) ----
    for (int e4 = tid; e4 < (SLEN * HD) / 4; e4 += 512) {
        int s  = e4 >> 3;
        int dq = (e4 & 7) * 4;
        float4 v = *reinterpret_cast<const float4*>(
            QKV + ((size_t)s * 16 + b) * 768 + koff + dq);
        int g = s >> 2;
        int sj = s & 3;
        sK[(dq + 0) * 1024 + ((g ^ ((dq + 0) >> 2)) << 2) + sj] = v.x;
        sK[(dq + 1) * 1024 + ((g ^ ((dq + 1) >> 2)) << 2) + sj] = v.y;
        sK[(dq + 2) * 1024 + ((g ^ ((dq + 2) >> 2)) << 2) + sj] = v.z;
        sK[(dq + 3) * 1024 + ((g ^ ((dq + 3) >> 2)) << 2) + sj] = v.w;
    }
    __syncthreads();

    for (int blk0 = 0; blk0 < 32; blk0++) {
        const int blk = (blk0 + wid * 2) & 31;   // stagger warps' phases
        const int t0 = wid * 64 + blk * 2;

        float qv0 = QKV[((size_t)(t0 + 0) * 16 + b) * 768 + qoff + lane];
        float qv1 = QKV[((size_t)(t0 + 1) * 16 + b) * 768 + qoff + lane];

        u64 acc2[2][16];
#pragma unroll
        for (int r = 0; r < 2; r++)
#pragma unroll
            for (int j = 0; j < 16; j++) acc2[r][j] = 0ull;

#pragma unroll 4
        for (int d = 0; d < 32; d++) {
            float q0 = __shfl_sync(0xffffffffu, qv0, d);
            float q1 = __shfl_sync(0xffffffffu, qv1, d);
            u64 qq0 = pk2(q0, q0);
            u64 qq1 = pk2(q1, q1);
            const float* basep = sK + d * 1024 + ((lane ^ (d >> 2)) << 2);
#pragma unroll
            for (int c = 0; c < 8; c++) {
                ulonglong2 k4 = *reinterpret_cast<const ulonglong2*>(basep + c * 128);
                fma2(acc2[0][2 * c + 0], qq0, k4.x);
                fma2(acc2[0][2 * c + 1], qq0, k4.y);
                fma2(acc2[1][2 * c + 0], qq1, k4.x);
                fma2(acc2[1][2 * c + 1], qq1, k4.y);
            }
        }

#pragma unroll 1
        for (int r = 0; r < 2; r++) {
            float a[32];
#pragma unroll
            for (int c = 0; c < 8; c++) {
                float2 p0 = up2(acc2[r][2 * c + 0]);
                float2 p1 = up2(acc2[r][2 * c + 1]);
                a[4 * c + 0] = p0.x; a[4 * c + 1] = p0.y;
                a[4 * c + 2] = p1.x; a[4 * c + 3] = p1.y;
            }

            // Michelot from tau = max(z) - 1 (valid support superset)
            float mx = a[0];
#pragma unroll
            for (int i = 1; i < 32; i++) mx = fmaxf(mx, a[i]);
#pragma unroll
            for (int o = 16; o > 0; o >>= 1)
                mx = fmaxf(mx, __shfl_xor_sync(0xffffffffu, mx, o));
            float tau = mx - 1.0f;
            int prevc = -1;

            for (int iter = 0; iter < 64; iter++) {
                float s = 0.f;
                int   c = 0;
#pragma unroll
                for (int i = 0; i < 32; i++) {
                    if (a[i] > tau) { s += a[i]; c++; }
                }
#pragma unroll
                for (int o = 16; o > 0; o >>= 1) {
                    s += __shfl_xor_sync(0xffffffffu, s, o);
                    c += __shfl_xor_sync(0xffffffffu, c, o);
                }
                if (c == prevc) break;
                tau = (s - 1.0f) / (float)c;
                prevc = c;
            }

            const int t = t0 + r;
            float* awrow = attnw + ((size_t)b * TLEN + t) * SLEN;
            const float* Vbase = QKV + (size_t)voff + (size_t)b * 768;
            float outv = 0.f;
#pragma unroll
            for (int i = 0; i < 32; i++) {
                float w = (a[i] > tau) ? (a[i] - tau) : 0.f;
                unsigned m = __ballot_sync(0xffffffffu, w > 0.f);
                if (w > 0.f) {
                    int s_me = (i >> 2) * 128 + lane * 4 + (i & 3);
                    atomicAdd(awrow + s_me, 0.125f * w);
                }
                while (m) {
                    int j = __ffs(m) - 1;
                    m &= m - 1;
                    float wj = __shfl_sync(0xffffffffu, w, j);
                    int s = (i >> 2) * 128 + j * 4 + (i & 3);
                    outv = fmaf(wj, Vbase[(size_t)s * 12288 + lane], outv);
                }
            }
            g_ctx[((size_t)t * BSZ + b) * EMB + h * HD + lane] = outv;
        }
    }
}

// ---------------- launcher ---------------------------------------------------
extern "C" void kernel_launch(void* const* d_in, const int* in_sizes, int n_in,
                              void* d_out, int out_size)
{
    const float* query = (const float*)d_in[0];
    const float* key   = (const float*)d_in[1];
    const float* value = (const float*)d_in[2];
    const float* Win   = (const float*)d_in[3];
    const float* bin   = (const float*)d_in[4];
    const float* Wout  = (const float*)d_in[5];
    const float* bout  = (const float*)d_in[6];

    float* outp  = (float*)d_out;                         // [1024,16,256]
    float* attnw = outp + (size_t)MROWS * EMB;            // [16,1024,1024]

    const int ATTN_SMEM = 32 * 1024 * (int)sizeof(float);
    cudaFuncSetAttribute(attn_kernel, cudaFuncAttributeMaxDynamicSharedMemorySize,
                         ATTN_SMEM);

    // 1) zero averaged attention-weights output (sparse atomics accumulate into it)
    zero_f4<<<2048, 256>>>((float4*)attnw, (int)((size_t)BSZ * TLEN * SLEN / 4));

    // 2) QKV projection (M=16384, N=768, K=256)
    gemm_k<0><<<dim3(768 / 128, MROWS / 128), 256>>>(query, key, value, Win, bin, nullptr);

    // 3) fused attention: scores + sparsemax + AV + avg attn weights
    attn_kernel<<<BH, 512, ATTN_SMEM>>>(attnw);

    // 4) output projection (M=16384, N=256, K=256)
    gemm_k<1><<<dim3(256 / 128, MROWS / 128), 256>>>(nullptr, nullptr, nullptr, Wout, bout, outp);
}

// round 10
// speedup vs baseline: 1.2742x; 1.1263x over previous
#include <cuda_runtime.h>
#include <cuda_bf16.h>
#include <cstdint>

// Problem constants
#define TLEN   1024
#define SLEN   1024
#define BSZ    16
#define EMB    256
#define NH     8
#define HD     32
#define BH     (BSZ*NH)        // 128
#define MROWS  (TLEN*BSZ)      // 16384
#define QSCALE 0.17677669529663688f   // 1/sqrt(32)

typedef unsigned long long u64;

// ---- packed fp32x2 helpers (attn kernel) ------------------------------------
__device__ __forceinline__ u64 pk2(float x, float y) {
    u64 r; asm("mov.b64 %0, {%1,%2};" : "=l"(r) : "f"(x), "f"(y)); return r;
}
__device__ __forceinline__ void fma2(u64& d, u64 a, u64 b) {
    asm("fma.rn.f32x2 %0, %1, %2, %0;" : "+l"(d) : "l"(a), "l"(b));
}
__device__ __forceinline__ float2 up2(u64 v) {
    float2 r; asm("mov.b64 {%0,%1}, %2;" : "=f"(r.x), "=f"(r.y) : "l"(v)); return r;
}
__device__ __forceinline__ uint32_t smem_u32(const void* p) {
    uint32_t a;
    asm("{ .reg .u64 t; cvta.to.shared.u64 t, %1; cvt.u32.u64 %0, t; }"
        : "=r"(a) : "l"(p));
    return a;
}

// ---- mma.sync helpers (base ISA; sm_103 target has no tcgen05) --------------
__device__ __forceinline__ void ldmx4(uint32_t r[4], uint32_t addr) {
    asm volatile("ldmatrix.sync.aligned.m8n8.x4.shared.b16 {%0,%1,%2,%3}, [%4];"
                 : "=r"(r[0]), "=r"(r[1]), "=r"(r[2]), "=r"(r[3]) : "r"(addr));
}
__device__ __forceinline__ void mma_bf16(float d[4], const uint32_t a[4],
                                         uint32_t b0, uint32_t b1) {
    asm volatile(
        "mma.sync.aligned.m16n8k16.row.col.f32.bf16.bf16.f32 "
        "{%0,%1,%2,%3}, {%4,%5,%6,%7}, {%8,%9}, {%0,%1,%2,%3};"
        : "+f"(d[0]), "+f"(d[1]), "+f"(d[2]), "+f"(d[3])
        : "r"(a[0]), "r"(a[1]), "r"(a[2]), "r"(a[3]), "r"(b0), "r"(b1));
}

// ---------------- scratch (device globals; no allocation allowed) ----------
__device__ float g_QKV[(size_t)MROWS * 768];   // [t*16+b][sec*256 + h*32 + d], q pre-scaled
__device__ float g_ctx[(size_t)MROWS * EMB];   // [t*16+b][h*32+d]

// ---------------- zero kernel ----------------------------------------------
__global__ void zero_f4(float4* __restrict__ p, int n4) {
    int i = blockIdx.x * blockDim.x + threadIdx.x;
    int stride = gridDim.x * blockDim.x;
    float4 z = make_float4(0.f, 0.f, 0.f, 0.f);
    for (; i < n4; i += stride) p[i] = z;
}

// ---------------- bf16-split HMMA GEMM:  out = X.W^T + b --------------------
// CTA = 128x128 tile, K=256 in four 64-chunks.
// Split: X=Xh+Xl, W=Wh+Wl (bf16); acc += Xh*Wh + Xh*Wl + Xl*Wh (fp32).
// smem tiles 128x64 bf16, 16B-chunk XOR swizzle: chunk' = chunk ^ (row&7).
// MODE 0: out -> g_QKV (q section scaled), X per 256-wide n-section
// MODE 1: X = g_ctx, out -> outp[r*256+n]
#define GM_SMEM 65536

__device__ __forceinline__ void conv_store_g(float4 x, char* hi, char* lo,
                                             int row, int kg4) {
    __nv_bfloat162 h01 = __floats2bfloat162_rn(x.x, x.y);
    __nv_bfloat162 h23 = __floats2bfloat162_rn(x.z, x.w);
    float r0 = x.x - __bfloat162float(h01.x);
    float r1 = x.y - __bfloat162float(h01.y);
    float r2 = x.z - __bfloat162float(h23.x);
    float r3 = x.w - __bfloat162float(h23.y);
    __nv_bfloat162 l01 = __floats2bfloat162_rn(r0, r1);
    __nv_bfloat162 l23 = __floats2bfloat162_rn(r2, r3);
    int c  = kg4 >> 3;                       // 16B chunk (8 halves)
    int sw = row * 128 + ((c ^ (row & 7)) << 4) + ((kg4 & 7) * 2);
    u64 hp = (u64)(*reinterpret_cast<uint32_t*>(&h01)) |
             ((u64)(*reinterpret_cast<uint32_t*>(&h23)) << 32);
    u64 lp = (u64)(*reinterpret_cast<uint32_t*>(&l01)) |
             ((u64)(*reinterpret_cast<uint32_t*>(&l23)) << 32);
    *reinterpret_cast<u64*>(hi + sw) = hp;
    *reinterpret_cast<u64*>(lo + sw) = lp;
}

template<int MODE>
__global__ __launch_bounds__(256)
void gemm_mma(const float* __restrict__ Xq, const float* __restrict__ Xk,
              const float* __restrict__ Xv, const float* __restrict__ W,
              const float* __restrict__ bias, float* __restrict__ outp)
{
    extern __shared__ __align__(128) char smem[];
    char* Ah = smem;
    char* Al = smem + 16384;
    char* Bh = smem + 32768;
    char* Bl = smem + 49152;

    const int tid  = threadIdx.x;
    const int lane = tid & 31;
    const int wid  = tid >> 5;
    const int mw   = (wid & 3) * 32;     // warp m offset in tile
    const int nw   = (wid >> 2) * 64;    // warp n offset in tile
    const int n0 = blockIdx.x * 128;
    const int m0 = blockIdx.y * 128;

    const float* X;
    if (MODE == 0) {
        int sec = n0 >> 8;
        X = (sec == 0) ? Xq : (sec == 1 ? Xk : Xv);
    } else {
        X = g_ctx;   // device-symbol reference
    }

    const uint32_t sA = smem_u32(Ah), sAl = smem_u32(Al);
    const uint32_t sB = smem_u32(Bh), sBl = smem_u32(Bl);

    float d[2][8][4];
#pragma unroll
    for (int mt = 0; mt < 2; mt++)
#pragma unroll
        for (int nt = 0; nt < 8; nt++)
#pragma unroll
            for (int j = 0; j < 4; j++) d[mt][nt][j] = 0.f;

    // fragment smem addresses (lane-dependent parts precomputed)
    // A frag (m16k16): row = mbase + (lane&15), chunk = 2ks + (lane>>4)
    const int arow = lane & 15;
    const int acs  = lane >> 4;
    // B frag (n16k16): row = nbase + (lane&7) + ((lane>>4)<<3), chunk = 2ks + ((lane>>3)&1)
    const int brow = (lane & 7) + ((lane >> 4) << 3);
    const int bcs  = (lane >> 3) & 1;
    const int lxor = lane & 7;

    for (int kc = 0; kc < 4; kc++) {
        // ---- fill A and B (f32 -> bf16 hi/lo) ----
#pragma unroll
        for (int g = tid, it = 0; it < 8; g += 256, it++) {
            int row = g >> 4;
            int kg4 = (g & 15) * 4;
            float4 xa = *reinterpret_cast<const float4*>(
                X + (size_t)(m0 + row) * 256 + kc * 64 + kg4);
            conv_store_g(xa, Ah, Al, row, kg4);
            float4 xb = *reinterpret_cast<const float4*>(
                W + (size_t)(n0 + row) * 256 + kc * 64 + kg4);
            conv_store_g(xb, Bh, Bl, row, kg4);
        }
        __syncthreads();

        // ---- 4 k16 steps x 3 splits ----
#pragma unroll
        for (int ks = 0; ks < 4; ks++) {
            uint32_t ah[2][4], al[2][4], bh[4][4], bl[4][4];
#pragma unroll
            for (int mt = 0; mt < 2; mt++) {
                int row = mw + mt * 16 + arow;
                uint32_t off = (uint32_t)(row * 128 + (((2 * ks + acs) ^ lxor) << 4));
                ldmx4(ah[mt], sA + off);
                ldmx4(al[mt], sAl + off);
            }
#pragma unroll
            for (int nt4 = 0; nt4 < 4; nt4++) {
                int row = nw + nt4 * 16 + brow;
                uint32_t off = (uint32_t)(row * 128 + (((2 * ks + bcs) ^ lxor) << 4));
                ldmx4(bh[nt4], sB + off);
                ldmx4(bl[nt4], sBl + off);
            }
#pragma unroll
            for (int mt = 0; mt < 2; mt++)
#pragma unroll
                for (int nt4 = 0; nt4 < 4; nt4++) {
                    // hi*hi
                    mma_bf16(d[mt][nt4 * 2 + 0], ah[mt], bh[nt4][0], bh[nt4][1]);
                    mma_bf16(d[mt][nt4 * 2 + 1], ah[mt], bh[nt4][2], bh[nt4][3]);
                    // hi*lo
                    mma_bf16(d[mt][nt4 * 2 + 0], ah[mt], bl[nt4][0], bl[nt4][1]);
                    mma_bf16(d[mt][nt4 * 2 + 1], ah[mt], bl[nt4][2], bl[nt4][3]);
                    // lo*hi
                    mma_bf16(d[mt][nt4 * 2 + 0], al[mt], bh[nt4][0], bh[nt4][1]);
                    mma_bf16(d[mt][nt4 * 2 + 1], al[mt], bh[nt4][2], bh[nt4][3]);
                }
        }
        __syncthreads();
    }

    // ---- epilogue: bias (+scale), float2 stores ----
    const float scl = (MODE == 0 && n0 < 256) ? QSCALE : 1.0f;
    const int qrow = lane >> 2;
    const int qcol = (lane & 3) * 2;
#pragma unroll
    for (int mt = 0; mt < 2; mt++) {
#pragma unroll
        for (int nt = 0; nt < 8; nt++) {
            int n = n0 + nw + nt * 8 + qcol;
            float2 bv = *reinterpret_cast<const float2*>(bias + n);
            int r0 = m0 + mw + mt * 16 + qrow;
#pragma unroll
            for (int hfl = 0; hfl < 2; hfl++) {
                int r = r0 + hfl * 8;
                float2 v;
                v.x = (d[mt][nt][hfl * 2 + 0] + bv.x) * scl;
                v.y = (d[mt][nt][hfl * 2 + 1] + bv.y) * scl;
                float* dst = (MODE == 0) ? (g_QKV + (size_t)r * 768 + n)
                                         : (outp  + (size_t)r * 256 + n);
                *reinterpret_cast<float2*>(dst) = v;
            }
        }
    }
}

// ---------------- fused attention (round-6 verbatim: best known, 830us) -----
__global__ __launch_bounds__(512, 1)
void attn_kernel(float* __restrict__ attnw /* [16,1024,1024] */)
{
    extern __shared__ float sK[];   // 32*1024 floats
    const int bh   = blockIdx.x;
    const int tid  = threadIdx.x;
    const int lane = tid & 31;
    const int wid  = tid >> 5;      // 0..15
    const int b    = bh >> 3;
    const int h    = bh & 7;

    const float* QKV = g_QKV;
    const int qoff = h * 32;
    const int koff = 256 + h * 32;
    const int voff = 512 + h * 32;

    for (int e4 = tid; e4 < (SLEN * HD) / 4; e4 += 512) {
        int s  = e4 >> 3;
        int dq = (e4 & 7) * 4;
        float4 v = *reinterpret_cast<const float4*>(
            QKV + ((size_t)s * 16 + b) * 768 + koff + dq);
        int g = s >> 2;
        int sj = s & 3;
        sK[(dq + 0) * 1024 + ((g ^ ((dq + 0) >> 2)) << 2) + sj] = v.x;
        sK[(dq + 1) * 1024 + ((g ^ ((dq + 1) >> 2)) << 2) + sj] = v.y;
        sK[(dq + 2) * 1024 + ((g ^ ((dq + 2) >> 2)) << 2) + sj] = v.z;
        sK[(dq + 3) * 1024 + ((g ^ ((dq + 3) >> 2)) << 2) + sj] = v.w;
    }
    __syncthreads();

    for (int blk0 = 0; blk0 < 32; blk0++) {
        const int blk = (blk0 + wid * 2) & 31;
        const int t0 = wid * 64 + blk * 2;

        float qv0 = QKV[((size_t)(t0 + 0) * 16 + b) * 768 + qoff + lane];
        float qv1 = QKV[((size_t)(t0 + 1) * 16 + b) * 768 + qoff + lane];

        u64 acc2[2][16];
#pragma unroll
        for (int r = 0; r < 2; r++)
#pragma unroll
            for (int j = 0; j < 16; j++) acc2[r][j] = 0ull;

#pragma unroll 4
        for (int d = 0; d < 32; d++) {
            float q0 = __shfl_sync(0xffffffffu, qv0, d);
            float q1 = __shfl_sync(0xffffffffu, qv1, d);
            u64 qq0 = pk2(q0, q0);
            u64 qq1 = pk2(q1, q1);
            const float* basep = sK + d * 1024 + ((lane ^ (d >> 2)) << 2);
#pragma unroll
            for (int c = 0; c < 8; c++) {
                ulonglong2 k4 = *reinterpret_cast<const ulonglong2*>(basep + c * 128);
                fma2(acc2[0][2 * c + 0], qq0, k4.x);
                fma2(acc2[0][2 * c + 1], qq0, k4.y);
                fma2(acc2[1][2 * c + 0], qq1, k4.x);
                fma2(acc2[1][2 * c + 1], qq1, k4.y);
            }
        }

#pragma unroll 1
        for (int r = 0; r < 2; r++) {
            float a[32];
#pragma unroll
            for (int c = 0; c < 8; c++) {
                float2 p0 = up2(acc2[r][2 * c + 0]);
                float2 p1 = up2(acc2[r][2 * c + 1]);
                a[4 * c + 0] = p0.x; a[4 * c + 1] = p0.y;
                a[4 * c + 2] = p1.x; a[4 * c + 3] = p1.y;
            }

            float mx = a[0];
#pragma unroll
            for (int i = 1; i < 32; i++) mx = fmaxf(mx, a[i]);
#pragma unroll
            for (int o = 16; o > 0; o >>= 1)
                mx = fmaxf(mx, __shfl_xor_sync(0xffffffffu, mx, o));
            float tau = mx - 1.0f;
            int prevc = -1;

            for (int iter = 0; iter < 64; iter++) {
                float s = 0.f;
                int   c = 0;
#pragma unroll
                for (int i = 0; i < 32; i++) {
                    if (a[i] > tau) { s += a[i]; c++; }
                }
#pragma unroll
                for (int o = 16; o > 0; o >>= 1) {
                    s += __shfl_xor_sync(0xffffffffu, s, o);
                    c += __shfl_xor_sync(0xffffffffu, c, o);
                }
                if (c == prevc) break;
                tau = (s - 1.0f) / (float)c;
                prevc = c;
            }

            const int t = t0 + r;
            float* awrow = attnw + ((size_t)b * TLEN + t) * SLEN;
            const float* Vbase = QKV + (size_t)voff + (size_t)b * 768;
            float outv = 0.f;
#pragma unroll
            for (int i = 0; i < 32; i++) {
                float w = (a[i] > tau) ? (a[i] - tau) : 0.f;
                unsigned m = __ballot_sync(0xffffffffu, w > 0.f);
                if (w > 0.f) {
                    int s_me = (i >> 2) * 128 + lane * 4 + (i & 3);
                    atomicAdd(awrow + s_me, 0.125f * w);
                }
                while (m) {
                    int j = __ffs(m) - 1;
                    m &= m - 1;
                    float wj = __shfl_sync(0xffffffffu, w, j);
                    int s = (i >> 2) * 128 + j * 4 + (i & 3);
                    outv = fmaf(wj, Vbase[(size_t)s * 12288 + lane], outv);
                }
            }
            g_ctx[((size_t)t * BSZ + b) * EMB + h * HD + lane] = outv;
        }
    }
}

// ---------------- launcher ---------------------------------------------------
extern "C" void kernel_launch(void* const* d_in, const int* in_sizes, int n_in,
                              void* d_out, int out_size)
{
    const float* query = (const float*)d_in[0];
    const float* key   = (const float*)d_in[1];
    const float* value = (const float*)d_in[2];
    const float* Win   = (const float*)d_in[3];
    const float* bin   = (const float*)d_in[4];
    const float* Wout  = (const float*)d_in[5];
    const float* bout  = (const float*)d_in[6];

    float* outp  = (float*)d_out;                         // [1024,16,256]
    float* attnw = outp + (size_t)MROWS * EMB;            // [16,1024,1024]

    const int ATTN_SMEM = 32 * 1024 * (int)sizeof(float);
    cudaFuncSetAttribute(attn_kernel, cudaFuncAttributeMaxDynamicSharedMemorySize,
                         ATTN_SMEM);
    cudaFuncSetAttribute(gemm_mma<0>, cudaFuncAttributeMaxDynamicSharedMemorySize,
                         GM_SMEM);
    cudaFuncSetAttribute(gemm_mma<1>, cudaFuncAttributeMaxDynamicSharedMemorySize,
                         GM_SMEM);

    // 1) zero averaged attention-weights output (sparse atomics accumulate into it)
    zero_f4<<<2048, 256>>>((float4*)attnw, (int)((size_t)BSZ * TLEN * SLEN / 4));

    // 2) QKV projection (M=16384, N=768, K=256) on tensor cores (mma.sync)
    gemm_mma<0><<<dim3(6, MROWS / 128), 256, GM_SMEM>>>(query, key, value, Win, bin, nullptr);

    // 3) fused attention: scores + sparsemax + AV + avg attn weights
    attn_kernel<<<BH, 512, ATTN_SMEM>>>(attnw);

    // 4) output projection (M=16384, N=256, K=256) on tensor cores (mma.sync)
    gemm_mma<1><<<dim3(2, MROWS / 128), 256, GM_SMEM>>>(nullptr, nullptr, nullptr, Wout, bout, outp);
}

// round 11
// speedup vs baseline: 1.3841x; 1.0862x over previous
#include <cuda_runtime.h>
#include <cuda_bf16.h>
#include <cstdint>

// Problem constants
#define TLEN   1024
#define SLEN   1024
#define BSZ    16
#define EMB    256
#define NH     8
#define HD     32
#define BH     (BSZ*NH)        // 128
#define MROWS  (TLEN*BSZ)      // 16384
#define QSCALE 0.17677669529663688f   // 1/sqrt(32)

typedef unsigned long long u64;

__device__ __forceinline__ uint32_t smem_u32(const void* p) {
    uint32_t a;
    asm("{ .reg .u64 t; cvta.to.shared.u64 t, %1; cvt.u32.u64 %0, t; }"
        : "=r"(a) : "l"(p));
    return a;
}

// ---- mma.sync helpers (base ISA; sm_103 target has no tcgen05) --------------
__device__ __forceinline__ void ldmx4(uint32_t r[4], uint32_t addr) {
    asm volatile("ldmatrix.sync.aligned.m8n8.x4.shared.b16 {%0,%1,%2,%3}, [%4];"
                 : "=r"(r[0]), "=r"(r[1]), "=r"(r[2]), "=r"(r[3]) : "r"(addr));
}
__device__ __forceinline__ void mma_bf16(float d[4], const uint32_t a[4],
                                         uint32_t b0, uint32_t b1) {
    asm volatile(
        "mma.sync.aligned.m16n8k16.row.col.f32.bf16.bf16.f32 "
        "{%0,%1,%2,%3}, {%4,%5,%6,%7}, {%8,%9}, {%0,%1,%2,%3};"
        : "+f"(d[0]), "+f"(d[1]), "+f"(d[2]), "+f"(d[3])
        : "r"(a[0]), "r"(a[1]), "r"(a[2]), "r"(a[3]), "r"(b0), "r"(b1));
}

// ---------------- scratch (device globals; no allocation allowed) ----------
__device__ float g_QKV[(size_t)MROWS * 768];   // [t*16+b][sec*256+h*32+d], q pre-scaled
__device__ float g_ctx[(size_t)MROWS * EMB];   // [t*16+b][h*32+d]
// bf16 hi/lo splits of Q (scaled) and K, per-bh contiguous: [bh][t or s][32]
__device__ __align__(16) __nv_bfloat16 g_Qh[(size_t)BH*1024*32];
__device__ __align__(16) __nv_bfloat16 g_Ql[(size_t)BH*1024*32];
__device__ __align__(16) __nv_bfloat16 g_Kh[(size_t)BH*1024*32];
__device__ __align__(16) __nv_bfloat16 g_Kl[(size_t)BH*1024*32];

// ---------------- zero kernel ----------------------------------------------
__global__ void zero_f4(float4* __restrict__ p, int n4) {
    int i = blockIdx.x * blockDim.x + threadIdx.x;
    int stride = gridDim.x * blockDim.x;
    float4 z = make_float4(0.f, 0.f, 0.f, 0.f);
    for (; i < n4; i += stride) p[i] = z;
}

// ---------------- bf16-split HMMA GEMM:  out = X.W^T + b --------------------
// CTA = 128x128 tile, K=256 in four 64-chunks; 3 split products, fp32 acc.
// MODE 0: out -> g_QKV (+ bf16 hi/lo of q,k to g_Q*/g_K*), X per n-section
// MODE 1: X = g_ctx, out -> outp[r*256+n]
#define GM_SMEM 65536

__device__ __forceinline__ void conv_store_g(float4 x, char* hi, char* lo,
                                             int row, int kg4) {
    __nv_bfloat162 h01 = __floats2bfloat162_rn(x.x, x.y);
    __nv_bfloat162 h23 = __floats2bfloat162_rn(x.z, x.w);
    float r0 = x.x - __bfloat162float(h01.x);
    float r1 = x.y - __bfloat162float(h01.y);
    float r2 = x.z - __bfloat162float(h23.x);
    float r3 = x.w - __bfloat162float(h23.y);
    __nv_bfloat162 l01 = __floats2bfloat162_rn(r0, r1);
    __nv_bfloat162 l23 = __floats2bfloat162_rn(r2, r3);
    int c  = kg4 >> 3;
    int sw = row * 128 + ((c ^ (row & 7)) << 4) + ((kg4 & 7) * 2);
    u64 hp = (u64)(*reinterpret_cast<uint32_t*>(&h01)) |
             ((u64)(*reinterpret_cast<uint32_t*>(&h23)) << 32);
    u64 lp = (u64)(*reinterpret_cast<uint32_t*>(&l01)) |
             ((u64)(*reinterpret_cast<uint32_t*>(&l23)) << 32);
    *reinterpret_cast<u64*>(hi + sw) = hp;
    *reinterpret_cast<u64*>(lo + sw) = lp;
}

template<int MODE>
__global__ __launch_bounds__(256)
void gemm_mma(const float* __restrict__ Xq, const float* __restrict__ Xk,
              const float* __restrict__ Xv, const float* __restrict__ W,
              const float* __restrict__ bias, float* __restrict__ outp)
{
    extern __shared__ __align__(128) char smem[];
    char* Ah = smem;
    char* Al = smem + 16384;
    char* Bh = smem + 32768;
    char* Bl = smem + 49152;

    const int tid  = threadIdx.x;
    const int lane = tid & 31;
    const int wid  = tid >> 5;
    const int mw   = (wid & 3) * 32;
    const int nw   = (wid >> 2) * 64;
    const int n0 = blockIdx.x * 128;
    const int m0 = blockIdx.y * 128;

    const float* X;
    if (MODE == 0) {
        int sec = n0 >> 8;
        X = (sec == 0) ? Xq : (sec == 1 ? Xk : Xv);
    } else {
        X = g_ctx;
    }

    const uint32_t sA = smem_u32(Ah), sAl = smem_u32(Al);
    const uint32_t sB = smem_u32(Bh), sBl = smem_u32(Bl);

    float d[2][8][4];
#pragma unroll
    for (int mt = 0; mt < 2; mt++)
#pragma unroll
        for (int nt = 0; nt < 8; nt++)
#pragma unroll
            for (int j = 0; j < 4; j++) d[mt][nt][j] = 0.f;

    const int arow = lane & 15;
    const int acs  = lane >> 4;
    const int brow = (lane & 7) + ((lane >> 4) << 3);
    const int bcs  = (lane >> 3) & 1;
    const int lxor = lane & 7;

    for (int kc = 0; kc < 4; kc++) {
#pragma unroll
        for (int g = tid, it = 0; it < 8; g += 256, it++) {
            int row = g >> 4;
            int kg4 = (g & 15) * 4;
            float4 xa = *reinterpret_cast<const float4*>(
                X + (size_t)(m0 + row) * 256 + kc * 64 + kg4);
            conv_store_g(xa, Ah, Al, row, kg4);
            float4 xb = *reinterpret_cast<const float4*>(
                W + (size_t)(n0 + row) * 256 + kc * 64 + kg4);
            conv_store_g(xb, Bh, Bl, row, kg4);
        }
        __syncthreads();

#pragma unroll
        for (int ks = 0; ks < 4; ks++) {
            uint32_t ah[2][4], al[2][4], bh[4][4], bl[4][4];
#pragma unroll
            for (int mt = 0; mt < 2; mt++) {
                int row = mw + mt * 16 + arow;
                uint32_t off = (uint32_t)(row * 128 + (((2 * ks + acs) ^ lxor) << 4));
                ldmx4(ah[mt], sA + off);
                ldmx4(al[mt], sAl + off);
            }
#pragma unroll
            for (int nt4 = 0; nt4 < 4; nt4++) {
                int row = nw + nt4 * 16 + brow;
                uint32_t off = (uint32_t)(row * 128 + (((2 * ks + bcs) ^ lxor) << 4));
                ldmx4(bh[nt4], sB + off);
                ldmx4(bl[nt4], sBl + off);
            }
#pragma unroll
            for (int mt = 0; mt < 2; mt++)
#pragma unroll
                for (int nt4 = 0; nt4 < 4; nt4++) {
                    mma_bf16(d[mt][nt4 * 2 + 0], ah[mt], bh[nt4][0], bh[nt4][1]);
                    mma_bf16(d[mt][nt4 * 2 + 1], ah[mt], bh[nt4][2], bh[nt4][3]);
                    mma_bf16(d[mt][nt4 * 2 + 0], ah[mt], bl[nt4][0], bl[nt4][1]);
                    mma_bf16(d[mt][nt4 * 2 + 1], ah[mt], bl[nt4][2], bl[nt4][3]);
                    mma_bf16(d[mt][nt4 * 2 + 0], al[mt], bh[nt4][0], bh[nt4][1]);
                    mma_bf16(d[mt][nt4 * 2 + 1], al[mt], bh[nt4][2], bh[nt4][3]);
                }
        }
        __syncthreads();
    }

    // ---- epilogue ----
    const float scl = (MODE == 0 && n0 < 256) ? QSCALE : 1.0f;
    const int qrow = lane >> 2;
    const int qcol = (lane & 3) * 2;
#pragma unroll
    for (int mt = 0; mt < 2; mt++) {
#pragma unroll
        for (int nt = 0; nt < 8; nt++) {
            int n = n0 + nw + nt * 8 + qcol;
            float2 bv = *reinterpret_cast<const float2*>(bias + n);
            int r0 = m0 + mw + mt * 16 + qrow;
#pragma unroll
            for (int hfl = 0; hfl < 2; hfl++) {
                int r = r0 + hfl * 8;
                float2 v;
                v.x = (d[mt][nt][hfl * 2 + 0] + bv.x) * scl;
                v.y = (d[mt][nt][hfl * 2 + 1] + bv.y) * scl;
                float* dst = (MODE == 0) ? (g_QKV + (size_t)r * 768 + n)
                                         : (outp  + (size_t)r * 256 + n);
                *reinterpret_cast<float2*>(dst) = v;
                if (MODE == 0) {
                    int sec = n >> 8;
                    if (sec < 2) {
                        // bf16 hi/lo split for q (scaled) and k
                        int hh = (n >> 5) & 7, dd = n & 31;
                        int tt = r >> 4,      bb = r & 15;
                        size_t base = (((size_t)(bb * 8 + hh) << 10) + tt) * 32 + dd;
                        __nv_bfloat162 hi2 = __floats2bfloat162_rn(v.x, v.y);
                        float rx = v.x - __bfloat162float(hi2.x);
                        float ry = v.y - __bfloat162float(hi2.y);
                        __nv_bfloat162 lo2 = __floats2bfloat162_rn(rx, ry);
                        if (sec == 0) {
                            *reinterpret_cast<__nv_bfloat162*>(g_Qh + base) = hi2;
                            *reinterpret_cast<__nv_bfloat162*>(g_Ql + base) = lo2;
                        } else {
                            *reinterpret_cast<__nv_bfloat162*>(g_Kh + base) = hi2;
                            *reinterpret_cast<__nv_bfloat162*>(g_Kl + base) = lo2;
                        }
                    }
                }
            }
        }
    }
}

// ---------------- fused attention v2: HMMA scores + sparsemax + AV ----------
// 128 blocks (one per bh), 512 threads (16 warps).
// K hi/lo resident in smem (packed 2 s-rows per 128B row, XOR swizzle).
// 64 waves of 16 t-rows: warp w MMAs cols [64w,64w+64) -> smem score buffer;
// then warp w runs sparsemax/AV for row w (round-6 epilogue, unchanged).
// swizzled offset for (row s, 16B chunk c of 4):
__device__ __forceinline__ uint32_t swz64(int s, int c) {
    int p = s >> 1;
    int j = (((s & 1) << 2) | c) ^ (p & 7);
    return (uint32_t)(p * 128 + j * 16);
}

#define ATTN_SMEM (65536 + 65536 + 66048 + 1024 + 1024)

__global__ __launch_bounds__(512, 1)
void attn_kernel(float* __restrict__ attnw /* [16,1024,1024] */)
{
    extern __shared__ __align__(128) char smem[];
    char*  sKh = smem;                                   // 64KB
    char*  sKl = smem + 65536;                           // 64KB
    float* sS  = reinterpret_cast<float*>(smem + 131072); // 16 x 1032 f32
    char*  sQh = smem + 131072 + 66048;                  // 1KB
    char*  sQl = sQh + 1024;                             // 1KB

    const int bh   = blockIdx.x;
    const int tid  = threadIdx.x;
    const int lane = tid & 31;
    const int wid  = tid >> 5;      // 0..15
    const int b    = bh >> 3;
    const int h    = bh & 7;

    const uint32_t skh = smem_u32(sKh), skl = smem_u32(sKl);
    const uint32_t sqh = smem_u32(sQh), sql = smem_u32(sQl);

    // ---- load K[bh] hi/lo into packed-swizzled smem ----
    for (int idx = tid; idx < 4096; idx += 512) {
        int s = idx >> 2, c = idx & 3;
        uint32_t off = swz64(s, c);
        size_t gb = (((size_t)bh << 10) + s) * 32 + c * 8;
        *reinterpret_cast<uint4*>(sKh + off) =
            *reinterpret_cast<const uint4*>(g_Kh + gb);
        *reinterpret_cast<uint4*>(sKl + off) =
            *reinterpret_cast<const uint4*>(g_Kl + gb);
    }
    __syncthreads();

    const float* Vbase = g_QKV + (size_t)(512 + h * 32) + (size_t)b * 768;
    const int brow = (lane & 7) + ((lane >> 4) << 3);
    const int bcs  = (lane >> 3) & 1;
    const int arow = lane & 15;
    const int acs  = lane >> 4;

    for (int wave = 0; wave < 64; wave++) {
        const int t0 = wave * 16;

        // ---- fill Q tile (16 rows x 32 bf16, hi+lo) ----
        if (tid < 128) {
            int a = tid >> 6, q = tid & 63;
            int r = q >> 2, c = q & 3;
            size_t gb = (((size_t)bh << 10) + t0 + r) * 32 + c * 8;
            const __nv_bfloat16* src = (a ? g_Ql : g_Qh) + gb;
            char* dst = (a ? sQl : sQh) + swz64(r, c);
            *reinterpret_cast<uint4*>(dst) = *reinterpret_cast<const uint4*>(src);
        }
        __syncthreads();   // Q ready; also: prev epilogue sS reads complete

        // ---- MMA: warp wid covers score cols [wid*64, wid*64+64) ----
        uint32_t ah[2][4], al[2][4];
#pragma unroll
        for (int ks = 0; ks < 2; ks++) {
            uint32_t off = swz64(arow, 2 * ks + acs);
            ldmx4(ah[ks], sqh + off);
            ldmx4(al[ks], sql + off);
        }
        float d[8][4];
#pragma unroll
        for (int nt = 0; nt < 8; nt++)
#pragma unroll
            for (int j = 0; j < 4; j++) d[nt][j] = 0.f;

#pragma unroll
        for (int ks = 0; ks < 2; ks++) {
#pragma unroll
            for (int nt4 = 0; nt4 < 4; nt4++) {
                int srow = wid * 64 + nt4 * 16 + brow;
                uint32_t off = swz64(srow, 2 * ks + bcs);
                uint32_t bhf[4], blf[4];
                ldmx4(bhf, skh + off);
                ldmx4(blf, skl + off);
                mma_bf16(d[nt4 * 2 + 0], ah[ks], bhf[0], bhf[1]);
                mma_bf16(d[nt4 * 2 + 1], ah[ks], bhf[2], bhf[3]);
                mma_bf16(d[nt4 * 2 + 0], ah[ks], blf[0], blf[1]);
                mma_bf16(d[nt4 * 2 + 1], ah[ks], blf[2], blf[3]);
                mma_bf16(d[nt4 * 2 + 0], al[ks], bhf[0], bhf[1]);
                mma_bf16(d[nt4 * 2 + 1], al[ks], bhf[2], bhf[3]);
            }
        }

        // ---- scatter fragments to score buffer ----
        {
            int rr = lane >> 2;
            int cb = wid * 64 + 2 * (lane & 3);
#pragma unroll
            for (int nt = 0; nt < 8; nt++) {
                *reinterpret_cast<float2*>(&sS[rr * 1032 + cb + nt * 8]) =
                    make_float2(d[nt][0], d[nt][1]);
                *reinterpret_cast<float2*>(&sS[(rr + 8) * 1032 + cb + nt * 8]) =
                    make_float2(d[nt][2], d[nt][3]);
            }
        }
        __syncthreads();   // scores ready

        // ---- sparsemax + AV + avg attn weights: warp wid owns row t0+wid ----
        {
            float a[32];
#pragma unroll
            for (int c = 0; c < 8; c++) {
                float4 v4 = *reinterpret_cast<const float4*>(
                    &sS[wid * 1032 + c * 128 + lane * 4]);
                a[c * 4 + 0] = v4.x; a[c * 4 + 1] = v4.y;
                a[c * 4 + 2] = v4.z; a[c * 4 + 3] = v4.w;
            }

            // Michelot from tau = max(z) - 1 (valid support superset)
            float mx = a[0];
#pragma unroll
            for (int i = 1; i < 32; i++) mx = fmaxf(mx, a[i]);
#pragma unroll
            for (int o = 16; o > 0; o >>= 1)
                mx = fmaxf(mx, __shfl_xor_sync(0xffffffffu, mx, o));
            float tau = mx - 1.0f;
            int prevc = -1;

            for (int iter = 0; iter < 64; iter++) {
                float s = 0.f;
                int   c = 0;
#pragma unroll
                for (int i = 0; i < 32; i++) {
                    if (a[i] > tau) { s += a[i]; c++; }
                }
#pragma unroll
                for (int o = 16; o > 0; o >>= 1) {
                    s += __shfl_xor_sync(0xffffffffu, s, o);
                    c += __shfl_xor_sync(0xffffffffu, c, o);
                }
                if (c == prevc) break;
                tau = (s - 1.0f) / (float)c;
                prevc = c;
            }

            const int t = t0 + wid;
            float* awrow = attnw + ((size_t)b * TLEN + t) * SLEN;
            float outv = 0.f;
#pragma unroll
            for (int i = 0; i < 32; i++) {
                float w = (a[i] > tau) ? (a[i] - tau) : 0.f;
                unsigned m = __ballot_sync(0xffffffffu, w > 0.f);
                if (w > 0.f) {
                    int s_me = (i >> 2) * 128 + lane * 4 + (i & 3);
                    atomicAdd(awrow + s_me, 0.125f * w);
                }
                while (m) {
                    int j = __ffs(m) - 1;
                    m &= m - 1;
                    float wj = __shfl_sync(0xffffffffu, w, j);
                    int s = (i >> 2) * 128 + j * 4 + (i & 3);
                    outv = fmaf(wj, Vbase[(size_t)s * 12288 + lane], outv);
                }
            }
            g_ctx[((size_t)t * BSZ + b) * EMB + h * HD + lane] = outv;
        }
    }
}

// ---------------- launcher ---------------------------------------------------
extern "C" void kernel_launch(void* const* d_in, const int* in_sizes, int n_in,
                              void* d_out, int out_size)
{
    const float* query = (const float*)d_in[0];
    const float* key   = (const float*)d_in[1];
    const float* value = (const float*)d_in[2];
    const float* Win   = (const float*)d_in[3];
    const float* bin   = (const float*)d_in[4];
    const float* Wout  = (const float*)d_in[5];
    const float* bout  = (const float*)d_in[6];

    float* outp  = (float*)d_out;                         // [1024,16,256]
    float* attnw = outp + (size_t)MROWS * EMB;            // [16,1024,1024]

    cudaFuncSetAttribute(attn_kernel, cudaFuncAttributeMaxDynamicSharedMemorySize,
                         ATTN_SMEM);
    cudaFuncSetAttribute(gemm_mma<0>, cudaFuncAttributeMaxDynamicSharedMemorySize,
                         GM_SMEM);
    cudaFuncSetAttribute(gemm_mma<1>, cudaFuncAttributeMaxDynamicSharedMemorySize,
                         GM_SMEM);

    // 1) zero averaged attention-weights output (sparse atomics accumulate into it)
    zero_f4<<<2048, 256>>>((float4*)attnw, (int)((size_t)BSZ * TLEN * SLEN / 4));

    // 2) QKV projection (M=16384, N=768, K=256) + bf16 hi/lo emit for Q,K
    gemm_mma<0><<<dim3(6, MROWS / 128), 256, GM_SMEM>>>(query, key, value, Win, bin, nullptr);

    // 3) fused attention: HMMA scores + sparsemax + AV + avg attn weights
    attn_kernel<<<BH, 512, ATTN_SMEM>>>(attnw);

    // 4) output projection (M=16384, N=256, K=256)
    gemm_mma<1><<<dim3(2, MROWS / 128), 256, GM_SMEM>>>(nullptr, nullptr, nullptr, Wout, bout, outp);
}